// round 1
// baseline (speedup 1.0000x reference)
#include <cuda_runtime.h>

#define NN 100000
#define NE 3200000
#define FF 256
#define FOUT 768

// ---------------- scratch (device globals — no allocation allowed) ----------
__device__ float g_Y1[NN * FF];   // x @ W1 + b1
__device__ float g_Y2[NN * FF];   // x @ W2 + b2
__device__ float g_T [NN * FF];   // A @ Y2 (intermediate for hop 2)
__device__ int   g_cnt[NN];
__device__ int   g_rowptr[NN + 1];
__device__ int   g_fill[NN];
__device__ int   g_bsum[128];
__device__ int   g_col[NE];
__device__ float g_val[NE];
__device__ int   g_is64;

// ---------------- index dtype detection (int64 vs int32) --------------------
__global__ void detect_kernel(const long long* __restrict__ row) {
    __shared__ int bad;
    if (threadIdx.x == 0) bad = 0;
    __syncthreads();
    const long long stride = (NE / 2) / 1024;  // stay in-bounds for int32 case
    int any = 0;
    #pragma unroll
    for (int s = 0; s < 4; s++) {
        long long idx = (long long)(threadIdx.x * 4 + s) * stride;
        long long v = row[idx];
        if (v < 0 || v >= NN) any = 1;
    }
    if (any) atomicOr(&bad, 1);
    __syncthreads();
    if (threadIdx.x == 0) g_is64 = (bad == 0) ? 1 : 0;
}

__device__ __forceinline__ int load_idx(const void* p, int e, int is64) {
    return is64 ? (int)((const long long*)p)[e] : ((const int*)p)[e];
}

// ---------------- CSR build -------------------------------------------------
__global__ void zero_cnt_kernel() {
    int i = blockIdx.x * blockDim.x + threadIdx.x;
    if (i < NN) g_cnt[i] = 0;
}

__global__ void hist_kernel(const void* __restrict__ rowp) {
    int is64 = g_is64;
    int stride = gridDim.x * blockDim.x;
    for (int e = blockIdx.x * blockDim.x + threadIdx.x; e < NE; e += stride) {
        int r = load_idx(rowp, e, is64);
        atomicAdd(&g_cnt[r], 1);
    }
}

// exclusive scan of g_cnt -> g_rowptr (3-kernel: block scan, block-sum scan, fixup)
__global__ void scan1_kernel() {
    __shared__ int sh[256];
    int t = threadIdx.x;
    int base = blockIdx.x * 1024 + t * 4;
    int v0 = (base + 0 < NN) ? g_cnt[base + 0] : 0;
    int v1 = (base + 1 < NN) ? g_cnt[base + 1] : 0;
    int v2 = (base + 2 < NN) ? g_cnt[base + 2] : 0;
    int v3 = (base + 3 < NN) ? g_cnt[base + 3] : 0;
    int s = v0 + v1 + v2 + v3;
    sh[t] = s;
    __syncthreads();
    for (int off = 1; off < 256; off <<= 1) {
        int x = (t >= off) ? sh[t - off] : 0;
        __syncthreads();
        sh[t] += x;
        __syncthreads();
    }
    int p = sh[t] - s;  // exclusive within block
    if (base + 0 < NN) g_rowptr[base + 0] = p; p += v0;
    if (base + 1 < NN) g_rowptr[base + 1] = p; p += v1;
    if (base + 2 < NN) g_rowptr[base + 2] = p; p += v2;
    if (base + 3 < NN) g_rowptr[base + 3] = p;
    if (t == 255) g_bsum[blockIdx.x] = sh[255];
}

__global__ void scan2_kernel() {
    __shared__ int sh[128];
    const int NB = (NN + 1023) / 1024;  // 98
    int t = threadIdx.x;
    int v = (t < NB) ? g_bsum[t] : 0;
    sh[t] = v;
    __syncthreads();
    for (int off = 1; off < 128; off <<= 1) {
        int x = (t >= off) ? sh[t - off] : 0;
        __syncthreads();
        sh[t] += x;
        __syncthreads();
    }
    g_bsum[t] = sh[t] - v;  // exclusive
}

__global__ void scan3_kernel() {
    int i = blockIdx.x * blockDim.x + threadIdx.x;
    if (i < NN) {
        int r = g_rowptr[i] + g_bsum[i >> 10];
        g_rowptr[i] = r;
        g_fill[i] = r;
    } else if (i == NN) {
        g_rowptr[NN] = NE;
    }
}

__global__ void scatter_kernel(const void* __restrict__ rowp,
                               const void* __restrict__ colp,
                               const float* __restrict__ vals) {
    int is64 = g_is64;
    int stride = gridDim.x * blockDim.x;
    for (int e = blockIdx.x * blockDim.x + threadIdx.x; e < NE; e += stride) {
        int r = load_idx(rowp, e, is64);
        int c = load_idx(colp, e, is64);
        int pos = atomicAdd(&g_fill[r], 1);
        g_col[pos] = c;
        g_val[pos] = vals[e];
    }
}

// ---------------- fused 3-way GEMM: [N,256] @ [256, 3x256] -----------------
// j=0 -> out[:, 0:256]; j=1 -> g_Y1; j=2 -> g_Y2.
#define BM 128
#define BN 128
#define BK 8

__global__ __launch_bounds__(256, 2)
void gemm_kernel(const float* __restrict__ X, const float* __restrict__ W,
                 const float* __restrict__ Bv, float* __restrict__ out) {
    __shared__ __align__(16) float As[BK][BM + 4];
    __shared__ __align__(16) float Bs[BK][BN];

    int tid = threadIdx.x;
    int m0 = blockIdx.x * BM;
    int n0 = blockIdx.y * BN;     // 0..767
    int j   = n0 >> 8;            // weight matrix index
    int nn0 = n0 & 255;           // column base within that matrix
    const float* Wj = W + j * (FF * FF);

    // global-load mapping
    int arow = tid >> 1;            // 0..127
    int acol = (tid & 1) << 2;      // 0 or 4
    int brow = tid >> 5;            // 0..7
    int bcol = (tid & 31) << 2;     // 0..124
    // compute mapping
    int tx = tid & 15;
    int ty = tid >> 4;

    float acc[8][8];
    #pragma unroll
    for (int a = 0; a < 8; a++)
        #pragma unroll
        for (int c = 0; c < 8; c++) acc[a][c] = 0.f;

    bool arow_ok = (m0 + arow) < NN;
    const float* aptr = X + (size_t)(m0 + arow) * FF + acol;
    const float* bptr = Wj + (size_t)brow * FF + nn0 + bcol;

    for (int kt = 0; kt < FF; kt += BK) {
        float4 av = arow_ok ? *(const float4*)(aptr + kt)
                            : make_float4(0.f, 0.f, 0.f, 0.f);
        float4 bv = *(const float4*)(bptr + (size_t)kt * FF);
        As[acol + 0][arow] = av.x;
        As[acol + 1][arow] = av.y;
        As[acol + 2][arow] = av.z;
        As[acol + 3][arow] = av.w;
        *(float4*)&Bs[brow][bcol] = bv;
        __syncthreads();
        #pragma unroll
        for (int k = 0; k < BK; k++) {
            float4 a0 = *(const float4*)&As[k][ty * 4];
            float4 a1 = *(const float4*)&As[k][64 + ty * 4];
            float4 b0 = *(const float4*)&Bs[k][tx * 4];
            float4 b1 = *(const float4*)&Bs[k][64 + tx * 4];
            float am[8] = {a0.x, a0.y, a0.z, a0.w, a1.x, a1.y, a1.z, a1.w};
            float bn[8] = {b0.x, b0.y, b0.z, b0.w, b1.x, b1.y, b1.z, b1.w};
            #pragma unroll
            for (int mi = 0; mi < 8; mi++)
                #pragma unroll
                for (int ni = 0; ni < 8; ni++)
                    acc[mi][ni] += am[mi] * bn[ni];
        }
        __syncthreads();
    }

    // bias + store
    const float* bb = Bv + j * 256 + nn0;
    float4 bias0 = *(const float4*)(bb + tx * 4);
    float4 bias1 = *(const float4*)(bb + 64 + tx * 4);

    float* cbase;
    int ldc;
    if (j == 0)      { cbase = out;  ldc = FOUT; }
    else if (j == 1) { cbase = g_Y1; ldc = FF;   }
    else             { cbase = g_Y2; ldc = FF;   }
    int ncol = nn0 + tx * 4;

    #pragma unroll
    for (int mi = 0; mi < 8; mi++) {
        int mm = (mi < 4) ? (ty * 4 + mi) : (64 + ty * 4 + mi - 4);
        int m = m0 + mm;
        if (m < NN) {
            float4 c0 = make_float4(acc[mi][0] + bias0.x, acc[mi][1] + bias0.y,
                                    acc[mi][2] + bias0.z, acc[mi][3] + bias0.w);
            float4 c1 = make_float4(acc[mi][4] + bias1.x, acc[mi][5] + bias1.y,
                                    acc[mi][6] + bias1.z, acc[mi][7] + bias1.w);
            *(float4*)(cbase + (size_t)m * ldc + ncol)      = c0;
            *(float4*)(cbase + (size_t)m * ldc + ncol + 64) = c1;
        }
    }
}

// ---------------- CSR SpMM: one warp per output row -------------------------
__device__ __forceinline__ void fma4(float4& a, float v, const float4& b) {
    a.x += v * b.x; a.y += v * b.y; a.z += v * b.z; a.w += v * b.w;
}

// pass 0: g_Y1 -> out[:,256:512]   (streamed)
// pass 1: g_Y2 -> g_T              (L2-resident)
// pass 2: g_T  -> out[:,512:768]   (streamed)
__global__ void spmm_kernel(float* __restrict__ out, int pass) {
    int gw = (blockIdx.x * blockDim.x + threadIdx.x) >> 5;
    if (gw >= NN) return;
    int lane = threadIdx.x & 31;

    const float* Y;
    float* O;
    int ldo;
    bool stream;
    if (pass == 0)      { Y = g_Y1; O = out + 256; ldo = FOUT; stream = true;  }
    else if (pass == 1) { Y = g_Y2; O = g_T;       ldo = FF;   stream = false; }
    else                { Y = g_T;  O = out + 512; ldo = FOUT; stream = true;  }

    int s = g_rowptr[gw];
    int e = g_rowptr[gw + 1];

    float4 acc0 = make_float4(0.f, 0.f, 0.f, 0.f);
    float4 acc1 = acc0;

    int i = s;
    for (; i + 2 <= e; i += 2) {
        int   c0 = g_col[i],     c1 = g_col[i + 1];
        float v0 = g_val[i],     v1 = g_val[i + 1];
        const float4* r0 = (const float4*)(Y + (size_t)c0 * FF) + lane;
        const float4* r1 = (const float4*)(Y + (size_t)c1 * FF) + lane;
        float4 x0 = r0[0], y0 = r0[32];
        float4 x1 = r1[0], y1 = r1[32];
        fma4(acc0, v0, x0); fma4(acc1, v0, y0);
        fma4(acc0, v1, x1); fma4(acc1, v1, y1);
    }
    if (i < e) {
        int   c0 = g_col[i];
        float v0 = g_val[i];
        const float4* r0 = (const float4*)(Y + (size_t)c0 * FF) + lane;
        fma4(acc0, v0, r0[0]);
        fma4(acc1, v0, r0[32]);
    }

    float* orow = O + (size_t)gw * ldo;
    if (stream) {
        __stwt((float4*)orow + lane, acc0);
        __stwt((float4*)orow + 32 + lane, acc1);
    } else {
        ((float4*)orow)[lane]      = acc0;
        ((float4*)orow)[32 + lane] = acc1;
    }
}

// ---------------- launch -----------------------------------------------------
extern "C" void kernel_launch(void* const* d_in, const int* in_sizes, int n_in,
                              void* d_out, int out_size) {
    const float* x    = (const float*)d_in[0];
    const float* W    = (const float*)d_in[1];
    const float* b    = (const float*)d_in[2];
    const void*  rowp = d_in[3];
    const void*  colp = d_in[4];
    const float* vals = (const float*)d_in[5];
    float* out = (float*)d_out;

    // CSR build (recomputed every launch; deterministic given inputs)
    detect_kernel<<<1, 256>>>((const long long*)rowp);
    zero_cnt_kernel<<<(NN + 255) / 256, 256>>>();
    hist_kernel<<<2048, 256>>>(rowp);
    scan1_kernel<<<(NN + 1023) / 1024, 256>>>();
    scan2_kernel<<<1, 128>>>();
    scan3_kernel<<<(NN + 1 + 255) / 256, 256>>>();
    scatter_kernel<<<2048, 256>>>(rowp, colp, vals);

    // three GEMMs fused into one launch over 768 output columns
    dim3 gg((NN + BM - 1) / BM, FOUT / BN);
    gemm_kernel<<<gg, 256>>>(x, W, b, out);

    // SpMM passes (kept separate so each 102 MB source stays L2-resident)
    int spblocks = (NN * 32 + 255) / 256;
    spmm_kernel<<<spblocks, 256>>>(out, 0);
    spmm_kernel<<<spblocks, 256>>>(out, 1);
    spmm_kernel<<<spblocks, 256>>>(out, 2);
}

// round 11
// speedup vs baseline: 1.2426x; 1.2426x over previous
#include <cuda_runtime.h>
#include <cuda_bf16.h>
#include <mma.h>
#include <cstdint>

using namespace nvcuda;

#define NN 100000
#define NE 3200000
#define FF 256
#define FOUT 768
#define MTILES 782            // 782*128 = 100096 >= NN

// ---------------- scratch (device globals — no allocation allowed) ----------
__device__ float g_Y1[NN * FF];   // x @ W1 + b1
__device__ float g_Y2[NN * FF];   // x @ W2 + b2
__device__ float g_T [NN * FF];   // A @ Y2 (intermediate for hop 2)
__device__ __nv_bfloat16 g_Ah[NN * FF];
__device__ __nv_bfloat16 g_Al[NN * FF];
__device__ __nv_bfloat16 g_Bh[FOUT * FF];   // [jn][k] = W[j][k][n] hi, jn = j*256+n
__device__ __nv_bfloat16 g_Bl[FOUT * FF];
__device__ int   g_cnt[NN];
__device__ int   g_rowptr[NN + 1];
__device__ int   g_fill[NN];
__device__ int   g_bsum[128];
__device__ int   g_col[NE];
__device__ float g_val[NE];
__device__ int   g_is64;

__device__ __forceinline__ uint32_t smem_u32(const void* p) {
    uint32_t a;
    asm("{ .reg .u64 t; cvta.to.shared.u64 t, %1; cvt.u32.u64 %0, t; }"
        : "=r"(a) : "l"(p));
    return a;
}

// cp.async 16B with zfill when pred==0 (src-size operand form)
__device__ __forceinline__ void cp_async16(uint32_t dst, const void* src, bool ok) {
    int sz = ok ? 16 : 0;
    asm volatile("cp.async.cg.shared.global [%0], [%1], 16, %2;"
                 :: "r"(dst), "l"(src), "r"(sz));
}
#define CP_COMMIT() asm volatile("cp.async.commit_group;")
#define CP_WAIT0()  asm volatile("cp.async.wait_group 0;" ::: "memory")

// ---------------- index dtype detection (int64 vs int32) --------------------
__global__ void detect_kernel(const long long* __restrict__ row) {
    __shared__ int bad;
    if (threadIdx.x == 0) bad = 0;
    __syncthreads();
    const long long stride = (NE / 2) / 1024;
    int any = 0;
    #pragma unroll
    for (int s = 0; s < 4; s++) {
        long long idx = (long long)(threadIdx.x * 4 + s) * stride;
        long long v = row[idx];
        if (v < 0 || v >= NN) any = 1;
    }
    if (any) atomicOr(&bad, 1);
    __syncthreads();
    if (threadIdx.x == 0) g_is64 = (bad == 0) ? 1 : 0;
}

__device__ __forceinline__ int load_idx(const void* p, int e, int is64) {
    return is64 ? (int)((const long long*)p)[e] : ((const int*)p)[e];
}

// ---------------- split kernels ---------------------------------------------
__global__ void splitA_kernel(const float* __restrict__ x) {
    int stride = gridDim.x * blockDim.x;
    for (int i = blockIdx.x * blockDim.x + threadIdx.x; i < NN * FF / 4; i += stride) {
        float4 a = ((const float4*)x)[i];
        __nv_bfloat16 h0 = __float2bfloat16(a.x), h1 = __float2bfloat16(a.y);
        __nv_bfloat16 h2 = __float2bfloat16(a.z), h3 = __float2bfloat16(a.w);
        __nv_bfloat16 l0 = __float2bfloat16(a.x - __bfloat162float(h0));
        __nv_bfloat16 l1 = __float2bfloat16(a.y - __bfloat162float(h1));
        __nv_bfloat16 l2 = __float2bfloat16(a.z - __bfloat162float(h2));
        __nv_bfloat16 l3 = __float2bfloat16(a.w - __bfloat162float(h3));
        ((__nv_bfloat162*)g_Ah)[i * 2 + 0] = __nv_bfloat162(h0, h1);
        ((__nv_bfloat162*)g_Ah)[i * 2 + 1] = __nv_bfloat162(h2, h3);
        ((__nv_bfloat162*)g_Al)[i * 2 + 0] = __nv_bfloat162(l0, l1);
        ((__nv_bfloat162*)g_Al)[i * 2 + 1] = __nv_bfloat162(l2, l3);
    }
}

__global__ void splitW_kernel(const float* __restrict__ W) {
    int o = blockIdx.x * blockDim.x + threadIdx.x;   // [jn][k]
    if (o >= FOUT * FF) return;
    int k = o & 255;
    int jn = o >> 8;
    int j = jn >> 8, n = jn & 255;
    float w = W[j * 65536 + k * 256 + n];
    __nv_bfloat16 h = __float2bfloat16(w);
    __nv_bfloat16 l = __float2bfloat16(w - __bfloat162float(h));
    g_Bh[o] = h;
    g_Bl[o] = l;
}

// ---------------- CSR build -------------------------------------------------
__global__ void zero_cnt_kernel() {
    int i = blockIdx.x * blockDim.x + threadIdx.x;
    if (i < NN) g_cnt[i] = 0;
}

__global__ void hist_kernel(const void* __restrict__ rowp) {
    int is64 = g_is64;
    int stride = gridDim.x * blockDim.x;
    for (int e = blockIdx.x * blockDim.x + threadIdx.x; e < NE; e += stride) {
        int r = load_idx(rowp, e, is64);
        atomicAdd(&g_cnt[r], 1);
    }
}

__global__ void scan1_kernel() {
    __shared__ int sh[256];
    int t = threadIdx.x;
    int base = blockIdx.x * 1024 + t * 4;
    int v0 = (base + 0 < NN) ? g_cnt[base + 0] : 0;
    int v1 = (base + 1 < NN) ? g_cnt[base + 1] : 0;
    int v2 = (base + 2 < NN) ? g_cnt[base + 2] : 0;
    int v3 = (base + 3 < NN) ? g_cnt[base + 3] : 0;
    int s = v0 + v1 + v2 + v3;
    sh[t] = s;
    __syncthreads();
    for (int off = 1; off < 256; off <<= 1) {
        int x = (t >= off) ? sh[t - off] : 0;
        __syncthreads();
        sh[t] += x;
        __syncthreads();
    }
    int p = sh[t] - s;
    if (base + 0 < NN) g_rowptr[base + 0] = p; p += v0;
    if (base + 1 < NN) g_rowptr[base + 1] = p; p += v1;
    if (base + 2 < NN) g_rowptr[base + 2] = p; p += v2;
    if (base + 3 < NN) g_rowptr[base + 3] = p;
    if (t == 255) g_bsum[blockIdx.x] = sh[255];
}

__global__ void scan2_kernel() {
    __shared__ int sh[128];
    const int NB = (NN + 1023) / 1024;
    int t = threadIdx.x;
    int v = (t < NB) ? g_bsum[t] : 0;
    sh[t] = v;
    __syncthreads();
    for (int off = 1; off < 128; off <<= 1) {
        int x = (t >= off) ? sh[t - off] : 0;
        __syncthreads();
        sh[t] += x;
        __syncthreads();
    }
    g_bsum[t] = sh[t] - v;
}

__global__ void scan3_kernel() {
    int i = blockIdx.x * blockDim.x + threadIdx.x;
    if (i < NN) {
        int r = g_rowptr[i] + g_bsum[i >> 10];
        g_rowptr[i] = r;
        g_fill[i] = r;
    } else if (i == NN) {
        g_rowptr[NN] = NE;
    }
}

__global__ void scatter_kernel(const void* __restrict__ rowp,
                               const void* __restrict__ colp,
                               const float* __restrict__ vals) {
    int is64 = g_is64;
    int stride = gridDim.x * blockDim.x;
    for (int e = blockIdx.x * blockDim.x + threadIdx.x; e < NE; e += stride) {
        int r = load_idx(rowp, e, is64);
        int c = load_idx(colp, e, is64);
        int pos = atomicAdd(&g_fill[r], 1);
        g_col[pos] = c;
        g_val[pos] = vals[e];
    }
}

// ---------------- wmma bf16-split GEMM (baseline sm_103 HMMA path) ----------
// Block tile 128(M) x 64(N); 12 N-tiles cover FOUT=768; j = ntile>>2.
// K=256 in 8 chunks of 32; double-buffered cp.async smem pipeline.
// D = Ah*Bh + Al*Bh + Ah*Bl, fp32 accumulate in wmma fragments.
#define BM 128
#define BN 64
#define KC 32
#define KCP 40                               // padded row (bf16 elems): conflict-free ldmatrix
#define ASZ (BM * KCP * 2)                   // 10240 bytes per A array
#define BSZ (BN * KCP * 2)                   // 5120 bytes per B array
#define BUFB (2 * ASZ + 2 * BSZ)             // 30720 bytes per pipeline buffer
#define BIAS_OFF (2 * BUFB)                  // 61440
#define GEMM_SMEM (BIAS_OFF + 16 * BN * 4)   // 65536

__device__ __forceinline__ void load_chunk_wmma(uint32_t sbase, int buf, int m0,
                                                int ntile, int c, int tid) {
    int k0 = c * KC;
    uint32_t bbase = sbase + buf * BUFB;
    // A hi/lo: 2 arrays x 128 rows x 4 vec16 = 1024 vec16
    #pragma unroll
    for (int it = 0; it < 4; it++) {
        int w = it * 256 + tid;
        int arr = w >> 9;                    // 0:Ah 1:Al
        int idx = w & 511;
        int row = idx >> 2;
        int col = (idx & 3) * 8;             // bf16 col
        const __nv_bfloat16* src =
            (arr ? g_Al : g_Ah) + (size_t)(m0 + row) * FF + k0 + col;
        uint32_t dst = bbase + arr * ASZ + row * (KCP * 2) + col * 2;
        cp_async16(dst, src, (m0 + row) < NN);
    }
    // B hi/lo: 2 arrays x 64 rows x 4 vec16 = 512 vec16 (row jn = ntile*64+row)
    #pragma unroll
    for (int it = 0; it < 2; it++) {
        int w = it * 256 + tid;
        int arr = w >> 8;                    // 0:Bh 1:Bl
        int idx = w & 255;
        int row = idx >> 2;
        int col = (idx & 3) * 8;
        const __nv_bfloat16* src =
            (arr ? g_Bl : g_Bh) + (size_t)(ntile * BN + row) * FF + k0 + col;
        uint32_t dst = bbase + 2 * ASZ + arr * BSZ + row * (KCP * 2) + col * 2;
        cp_async16(dst, src, true);
    }
}

__global__ __launch_bounds__(256, 2)
void gemm_wmma_kernel(const float* __restrict__ Bv, float* __restrict__ out) {
    extern __shared__ char smem[];
    uint32_t sbase = smem_u32(smem);
    int tid = threadIdx.x;
    int wid = tid >> 5;
    int m0 = blockIdx.x * BM;
    int ntile = blockIdx.y;                  // 0..11; j = ntile>>2
    int j = ntile >> 2;

    int wm = wid >> 1;                       // 0..3  -> rows wm*32
    int wn = wid & 1;                        // 0..1  -> cols wn*32
    int row0 = wm * 32;
    int col0 = wn * 32;

    // kick off chunk 0 loads, then fill bias tile (16 x BN f32, rows identical)
    load_chunk_wmma(sbase, 0, m0, ntile, 0, tid);
    CP_COMMIT();
    float* biasT = (float*)(smem + BIAS_OFF);
    #pragma unroll
    for (int it = 0; it < 4; it++) {
        int idx = it * 256 + tid;            // 0..1023
        int col = idx & 63;
        biasT[idx] = Bv[ntile * BN + col];
    }
    __syncthreads();

    // init accumulators from bias tile
    wmma::fragment<wmma::accumulator, 16, 16, 16, float> acc[2][2];
    #pragma unroll
    for (int i = 0; i < 2; i++)
        #pragma unroll
        for (int jf = 0; jf < 2; jf++)
            wmma::load_matrix_sync(acc[i][jf], biasT + (col0 + jf * 16), BN,
                                   wmma::mem_row_major);

    for (int c = 0; c < 8; c++) {
        CP_WAIT0();
        __syncthreads();
        if (c < 7) {
            load_chunk_wmma(sbase, (c + 1) & 1, m0, ntile, c + 1, tid);
            CP_COMMIT();
        }
        const char* bb = smem + (c & 1) * BUFB;
        const __nv_bfloat16* sAh = (const __nv_bfloat16*)(bb);
        const __nv_bfloat16* sAl = (const __nv_bfloat16*)(bb + ASZ);
        const __nv_bfloat16* sBh = (const __nv_bfloat16*)(bb + 2 * ASZ);
        const __nv_bfloat16* sBl = (const __nv_bfloat16*)(bb + 2 * ASZ + BSZ);
        #pragma unroll
        for (int ks = 0; ks < 2; ks++) {
            int kk = ks * 16;
            wmma::fragment<wmma::matrix_a, 16, 16, 16, __nv_bfloat16, wmma::row_major> aH[2], aL[2];
            wmma::fragment<wmma::matrix_b, 16, 16, 16, __nv_bfloat16, wmma::col_major> bH[2], bL[2];
            #pragma unroll
            for (int i = 0; i < 2; i++) {
                wmma::load_matrix_sync(aH[i], sAh + (row0 + i * 16) * KCP + kk, KCP);
                wmma::load_matrix_sync(aL[i], sAl + (row0 + i * 16) * KCP + kk, KCP);
            }
            #pragma unroll
            for (int jf = 0; jf < 2; jf++) {
                wmma::load_matrix_sync(bH[jf], sBh + (col0 + jf * 16) * KCP + kk, KCP);
                wmma::load_matrix_sync(bL[jf], sBl + (col0 + jf * 16) * KCP + kk, KCP);
            }
            #pragma unroll
            for (int i = 0; i < 2; i++)
                #pragma unroll
                for (int jf = 0; jf < 2; jf++) {
                    wmma::mma_sync(acc[i][jf], aH[i], bH[jf], acc[i][jf]);
                    wmma::mma_sync(acc[i][jf], aL[i], bH[jf], acc[i][jf]);
                    wmma::mma_sync(acc[i][jf], aH[i], bL[jf], acc[i][jf]);
                }
        }
        __syncthreads();   // compute on this buf done before loads overwrite it next iter
    }

    // epilogue: stage to smem (aliases pipeline buffers), then guarded writes
    float* stage = (float*)smem;             // 128 x 64 f32 = 32768 bytes
    #pragma unroll
    for (int i = 0; i < 2; i++)
        #pragma unroll
        for (int jf = 0; jf < 2; jf++)
            wmma::store_matrix_sync(stage + (row0 + i * 16) * BN + col0 + jf * 16,
                                    acc[i][jf], BN, wmma::mem_row_major);
    __syncthreads();

    int ncol0 = (ntile & 3) * BN;
    #pragma unroll
    for (int it = 0; it < 8; it++) {
        int w = it * 256 + tid;              // 0..2047
        int row = w >> 4;
        int col = (w & 15) * 4;
        int m = m0 + row;
        if (m < NN) {
            float4 v = *(float4*)(stage + row * BN + col);
            if (j == 0)
                __stwt((float4*)(out + (size_t)m * FOUT + ncol0 + col), v);
            else if (j == 1)
                *(float4*)(g_Y1 + (size_t)m * FF + ncol0 + col) = v;
            else
                *(float4*)(g_Y2 + (size_t)m * FF + ncol0 + col) = v;
        }
    }
}

// ---------------- CSR SpMM: one warp per output row -------------------------
__device__ __forceinline__ void fma4(float4& a, float v, const float4& b) {
    a.x += v * b.x; a.y += v * b.y; a.z += v * b.z; a.w += v * b.w;
}

__global__ void spmm_kernel(float* __restrict__ out, int pass) {
    int gw = (blockIdx.x * blockDim.x + threadIdx.x) >> 5;
    if (gw >= NN) return;
    int lane = threadIdx.x & 31;

    const float* Y;
    float* O;
    int ldo;
    bool stream;
    if (pass == 0)      { Y = g_Y1; O = out + 256; ldo = FOUT; stream = true;  }
    else if (pass == 1) { Y = g_Y2; O = g_T;       ldo = FF;   stream = false; }
    else                { Y = g_T;  O = out + 512; ldo = FOUT; stream = true;  }

    int s = g_rowptr[gw];
    int e = g_rowptr[gw + 1];

    float4 acc0 = make_float4(0.f, 0.f, 0.f, 0.f);
    float4 acc1 = acc0;

    int i = s;
    for (; i + 2 <= e; i += 2) {
        int   c0 = g_col[i],     c1 = g_col[i + 1];
        float v0 = g_val[i],     v1 = g_val[i + 1];
        const float4* r0 = (const float4*)(Y + (size_t)c0 * FF) + lane;
        const float4* r1 = (const float4*)(Y + (size_t)c1 * FF) + lane;
        float4 x0 = r0[0], y0 = r0[32];
        float4 x1 = r1[0], y1 = r1[32];
        fma4(acc0, v0, x0); fma4(acc1, v0, y0);
        fma4(acc0, v1, x1); fma4(acc1, v1, y1);
    }
    if (i < e) {
        int   c0 = g_col[i];
        float v0 = g_val[i];
        const float4* r0 = (const float4*)(Y + (size_t)c0 * FF) + lane;
        fma4(acc0, v0, r0[0]);
        fma4(acc1, v0, r0[32]);
    }

    float* orow = O + (size_t)gw * ldo;
    if (stream) {
        __stwt((float4*)orow + lane, acc0);
        __stwt((float4*)orow + 32 + lane, acc1);
    } else {
        ((float4*)orow)[lane]      = acc0;
        ((float4*)orow)[32 + lane] = acc1;
    }
}

// ---------------- launch -----------------------------------------------------
extern "C" void kernel_launch(void* const* d_in, const int* in_sizes, int n_in,
                              void* d_out, int out_size) {
    const float* x    = (const float*)d_in[0];
    const float* W    = (const float*)d_in[1];
    const float* b    = (const float*)d_in[2];
    const void*  rowp = d_in[3];
    const void*  colp = d_in[4];
    const float* vals = (const float*)d_in[5];
    float* out = (float*)d_out;

    cudaFuncSetAttribute(gemm_wmma_kernel,
                         cudaFuncAttributeMaxDynamicSharedMemorySize, GEMM_SMEM);

    // order chosen so ncu -s 5 -c 1 profiles gemm_wmma_kernel (6th launch)
    detect_kernel<<<1, 256>>>((const long long*)rowp);
    splitA_kernel<<<1024, 256>>>(x);
    splitW_kernel<<<(FOUT * FF + 255) / 256, 256>>>(W);
    zero_cnt_kernel<<<(NN + 255) / 256, 256>>>();
    hist_kernel<<<2048, 256>>>(rowp);

    dim3 gg(MTILES, FOUT / BN);              // 782 x 12
    gemm_wmma_kernel<<<gg, 256, GEMM_SMEM>>>(b, out);

    scan1_kernel<<<(NN + 1023) / 1024, 256>>>();
    scan2_kernel<<<1, 128>>>();
    scan3_kernel<<<(NN + 1 + 255) / 256, 256>>>();
    scatter_kernel<<<2048, 256>>>(rowp, colp, vals);

    int spblocks = (NN * 32 + 255) / 256;
    spmm_kernel<<<spblocks, 256>>>(out, 0);
    spmm_kernel<<<spblocks, 256>>>(out, 1);
    spmm_kernel<<<spblocks, 256>>>(out, 2);
}